// round 13
// baseline (speedup 1.0000x reference)
#include <cuda_runtime.h>
#include <cuda_bf16.h>
#include <math.h>

// Problem constants
#define BB 128
#define TT 256
#define DD 256
#define HH 256

#define NBLK 128        // 16 groups x (4 layer-1 CTAs + 4 layer-2 CTAs)
#define NGRP 16
#define NTH  512        // k_seq threads per CTA (16 warps)

typedef unsigned long long ull;

// ---------------- packed f32x2 helpers (Blackwell FFMA2 via PTX) ----------------
__device__ __forceinline__ ull pack2(float lo, float hi) {
    ull r; asm("mov.b64 %0, {%1, %2};" : "=l"(r) : "f"(lo), "f"(hi)); return r;
}
__device__ __forceinline__ void unpack2(float& lo, float& hi, ull v) {
    asm("mov.b64 {%0, %1}, %2;" : "=f"(lo), "=f"(hi) : "l"(v));
}
__device__ __forceinline__ ull fma2(ull a, ull b, ull c) {
    ull d; asm("fma.rn.f32x2 %0, %1, %2, %3;" : "=l"(d) : "l"(a), "l"(b), "l"(c));
    return d;
}

// ---------------- device scratch ----------------
// h tiles in GROUP-TILE layout: [t or buf][grp][col*8 + r] (2048 floats/tile)
__device__ float g_pre1[TT * BB * HH];          // pre1[t][b][h] row-major (incl b1)
__device__ float g_h1all[(long)TT * NGRP * 2048];  // h1[t], non-destructive
__device__ float g_h2t[2][NGRP * 2048];         // h2 ring, depth 2
__device__ float g_P[4][NGRP][4][2048];         // Wih2 partials: [ring][grp][src][r*256+j]
__device__ float g_h2rm[BB * HH];               // final forward h2, row-major
__device__ float g_h1bk[BB * HH];
__device__ float g_h2bk[BB * HH];
__device__ unsigned g_f1[NGRP * 32];            // h1 exchange flags (L1<->L1)
__device__ unsigned g_f1p[NGRP * 32];           // P-ready flags (L1 -> L2)
__device__ unsigned g_f2[NGRP * 32];            // h2 exchange flags (L2<->L2, + backpressure)

// ---------------- reset kernel (per-replay determinism) ----------------
__global__ void k_reset() {
    unsigned i = blockIdx.x * blockDim.x + threadIdx.x;
    if (i < NGRP * 32) { g_f1[i] = 0u; g_f1p[i] = 0u; g_f2[i] = 0u; }
}

// ---------------- release/acquire flag ops ----------------
__device__ __forceinline__ void signal(unsigned* p) {
    __syncthreads();   // all threads' stores precede the release
    if (threadIdx.x == 0)
        asm volatile("red.release.gpu.add.u32 [%0], 1;" :: "l"(p) : "memory");
}
// combined wait on two flags with one barrier
__device__ __forceinline__ void waitflag2(unsigned* pa, unsigned ta,
                                          unsigned* pb, unsigned tb) {
    if (threadIdx.x == 0) {
        unsigned v;
        do { asm volatile("ld.acquire.gpu.u32 %0, [%1];" : "=r"(v) : "l"(pa) : "memory");
        } while (v < ta);
        do { asm volatile("ld.acquire.gpu.u32 %0, [%1];" : "=r"(v) : "l"(pb) : "memory");
        } while (v < tb);
    }
    __syncthreads();
}

// ---------------- cp.async helpers ----------------
__device__ __forceinline__ unsigned smem_u32(const void* p) {
    unsigned a;
    asm("{ .reg .u64 t; cvta.to.shared.u64 t, %1; cvt.u32.u64 %0, t; }"
        : "=r"(a) : "l"(p));
    return a;
}
__device__ __forceinline__ void cpa16(unsigned saddr, const float* gaddr) {
    asm volatile("cp.async.cg.shared.global [%0], [%1], 16;"
                 :: "r"(saddr), "l"(gaddr) : "memory");
}
#define CPA_COMMIT()  asm volatile("cp.async.commit_group;" ::: "memory")
#define CPA_WAIT(n)   asm volatile("cp.async.wait_group %0;" :: "n"(n) : "memory")

// 256k x 64col weight tile -> smem sW[k*64 + c]
__device__ __forceinline__ void load_w_async(unsigned u_sW, const float* __restrict__ W,
                                             int col0, int tid) {
#pragma unroll
    for (int i = 0; i < 8; i++) {
        int chunk = tid + i * NTH;
        int k = chunk >> 4;
        int c4 = (chunk & 15) * 4;
        cpa16(u_sW + (unsigned)(k * 64 + c4) * 4, W + (long)k * HH + col0 + c4);
    }
}
// 64k(rows col0..col0+63) x 256col slice of Wih2 -> smem sWI[k*256 + j]
__device__ __forceinline__ void load_wI_async(unsigned u_sW, const float* __restrict__ W,
                                              int col0, int tid) {
#pragma unroll
    for (int i = 0; i < 8; i++) {
        int chunk = tid + i * NTH;          // 0..4095 float4 chunks
        int k = chunk >> 6;                  // 0..63 local k
        int j4 = chunk & 63;
        cpa16(u_sW + (unsigned)chunk * 16, W + (long)(col0 + k) * HH + j4 * 4);
    }
}

// ---------------- generic 64x64 register-blocked fp32 GEMM tile (FFMA2) ----------------
__device__ __forceinline__ void gemm64_body(
    const float* __restrict__ A, long lda,
    const float* __restrict__ A2, int ksplit, long lda2,
    const float* __restrict__ W, long ldw, int wtrans,
    const float* __restrict__ bias,
    float* __restrict__ C, long ldc,
    int K, int row0, int col0, int act,
    float* sA, float* sW)
{
    const int tid = threadIdx.x;
    const int tx = tid & 15;
    const int ty = tid >> 4;
    ull accp[4][2];
#pragma unroll
    for (int i = 0; i < 4; i++) { accp[i][0] = 0ull; accp[i][1] = 0ull; }

#pragma unroll 1
    for (int k0 = 0; k0 < K; k0 += 64) {
        const float* Ak = A; long ldak = lda; int kb = k0;
        if (A2 != nullptr && k0 >= ksplit) { Ak = A2; ldak = lda2; kb = k0 - ksplit; }

        __syncthreads();
#pragma unroll
        for (int p = 0; p < 4; p++) {
            int i = p * 256 + tid;
            int rr = i >> 4;
            int k4 = i & 15;
            float4 v = *(const float4*)(Ak + (long)(row0 + rr) * ldak + kb + k4 * 4);
            *(float4*)(sA + rr * 72 + k4 * 4) = v;
        }
        if (!wtrans) {
#pragma unroll
            for (int p = 0; p < 16; p++) {
                int i = p * 256 + tid;
                int kk = i >> 6, cc = i & 63;
                sW[kk * 72 + cc] = W[(long)(k0 + kk) * ldw + col0 + cc];
            }
        } else {
#pragma unroll
            for (int p = 0; p < 16; p++) {
                int i = p * 256 + tid;
                int kk = i & 63, cc = i >> 6;
                sW[kk * 72 + cc] = W[(long)(col0 + cc) * ldw + k0 + kk];
            }
        }
        __syncthreads();

#pragma unroll
        for (int k = 0; k < 64; k++) {
            ulonglong2 wv = *(const ulonglong2*)(sW + k * 72 + tx * 4);
#pragma unroll
            for (int i = 0; i < 4; i++) {
                float a = sA[(ty * 4 + i) * 72 + k];
                ull ap = pack2(a, a);
                accp[i][0] = fma2(ap, wv.x, accp[i][0]);
                accp[i][1] = fma2(ap, wv.y, accp[i][1]);
            }
        }
    }

#pragma unroll
    for (int i = 0; i < 4; i++) {
        float v0, v1, v2, v3;
        unpack2(v0, v1, accp[i][0]);
        unpack2(v2, v3, accp[i][1]);
        float vv[4] = {v0, v1, v2, v3};
#pragma unroll
        for (int j = 0; j < 4; j++) {
            int rr = row0 + ty * 4 + i;
            int cc = col0 + tx * 4 + j;
            float v = vv[j] + bias[cc];
            if (act) v = tanhf(v);
            C[(long)rr * ldc + cc] = v;
        }
    }
}

// ---------------- K1: precompute pre1[t] = x_t @ Wih_f[0,t] + b_f[0,t] ----------------
__global__ __launch_bounds__(256) void k_pre(
    const float* __restrict__ x, const float* __restrict__ Wih_f,
    const float* __restrict__ b_f)
{
    __shared__ float sA[64 * 72];
    __shared__ float sW[64 * 72];
    int t = blockIdx.y;
    int tile = blockIdx.x;
    int row0 = (tile >> 2) * 64;
    int col0 = (tile & 3) * 64;
    gemm64_body(x + (long)t * DD, (long)TT * DD,
                nullptr, 1 << 30, 0,
                Wih_f + (long)t * DD * HH, HH, 0,
                b_f + (long)t * HH,
                g_pre1 + (long)t * BB * HH, HH,
                DD, row0, col0, /*act=*/0, sA, sW);
}

// ================= K2: rebalanced layer-split wavefront =================
// L1 CTAs (sub 0-3) now ALSO compute the Wih2 split-K partials: their own 64
// h1-columns are exactly a 64-wide k-slice of h1[t] @ Wih2[t], available
// locally (no exchange). L2 CTAs (sub 4-7) just sum 4 partials + do the Whh2
// dot — the system period = L2 chain loses one full wait+stage+dot.
// P ring depth 4 with f2 backpressure. Weight cp.async issued AFTER staging
// loads (keeps critical LDGs out of the L1tex queue shadow).

// stage a 2048-float group tile (layout matches smem exactly)
__device__ __forceinline__ void stage(float* dst, const float* __restrict__ src,
                                      int tid) {
    float4 v = __ldcg((const float4*)(src + tid * 4));
    *(float4*)(dst + tid * 4) = v;
}

// packed dot over this thread's 32-k slice; h tile hsT[k*8+r], weights sW[k*64+c]
__device__ __forceinline__ void dot32s(const float* hsT, const float* sW,
                                       int s, int c,
                                       ull& a01, ull& a23, ull& a45, ull& a67) {
#pragma unroll
    for (int kk = 0; kk < 32; kk++) {
        int k = s * 32 + kk;
        const ulonglong2* p = (const ulonglong2*)(hsT + k * 8);
        ulonglong2 v0 = p[0];
        ulonglong2 v1 = p[1];
        float wk = sW[k * 64 + c];
        ull wp = pack2(wk, wk);
        a01 = fma2(v0.x, wp, a01);
        a23 = fma2(v0.y, wp, a23);
        a45 = fma2(v1.x, wp, a45);
        a67 = fma2(v1.y, wp, a67);
    }
}

// split-K reduce over 8 slices: thread (s,c) finalizes output (row=s, col=c)
__device__ __forceinline__ float reduce1(float* red, ull a01, ull a23, ull a45, ull a67,
                                         int s, int c) {
    float r[8];
    unpack2(r[0], r[1], a01);
    unpack2(r[2], r[3], a23);
    unpack2(r[4], r[5], a45);
    unpack2(r[6], r[7], a67);
#pragma unroll
    for (int q = 0; q < 8; q++) red[(s * 8 + q) * 64 + c] = r[q];
    __syncthreads();
    float v = 0.f;
#pragma unroll
    for (int q = 0; q < 8; q++) v += red[(q * 8 + s) * 64 + c];
    return v;
}

// dyn smem (floats): hsA 2048 | hsP 512 | red 4096 | W0 16384 | W1 16384 | WI 16384
#define SMEM_SEQ_BYTES ((2048 + 512 + 4096 + 16384 * 3) * 4)

__global__ __launch_bounds__(NTH, 1)
void k_seq(const float* __restrict__ Wih_f, const float* __restrict__ Whh_f,
           const float* __restrict__ b_f)
{
    extern __shared__ float dyn[];
    float* hsA = dyn;                   // L1: h1 tile | L2: h2 tile
    float* hsP = dyn + 2048;            // L1: local h1 columns [c*8+r]
    float* red = dyn + 2560;            // split-K scratch
    float* W0  = dyn + 6656;            // double buffer 0 (Whh1 / Whh2)
    float* W1  = W0 + 16384;            // double buffer 1
    float* WI  = W1 + 16384;            // L1: Wih2 k-slice [k*256+j] (single)
    const unsigned u_W0 = smem_u32(W0);
    const unsigned u_W1 = smem_u32(W1);
    const unsigned u_WI = smem_u32(WI);

    const int tid = threadIdx.x;
    const int s = tid >> 6;                              // 0..7 k-slice / out row
    const int c = tid & 63;                              // column
    const int pj = tid & 255;                            // dotP: output col 0..255
    const int ph = tid >> 8;                             // dotP: row half (0/1)
    const int grp = blockIdx.x >> 3;
    const int sub = blockIdx.x & 7;
    const int layer = sub >> 2;
    const int col0 = (sub & 3) * 64;
    const int row_base = grp * 8;
    const int tidx = (col0 + c) * 8 + s;                 // tile slot (row s)
    const int rm = (row_base + s) * HH + col0 + c;       // row-major (pre1)
    const long gtile = (long)grp * 2048;
    unsigned* f1  = &g_f1[grp * 32];
    unsigned* f1p = &g_f1p[grp * 32];
    unsigned* f2  = &g_f2[grp * 32];

    const float* Whh1 = Whh_f;
    const float* Wih2 = Wih_f + (long)TT * DD * HH;
    const float* Whh2 = Whh_f + (long)TT * HH * HH;
    const float* b2   = b_f + (long)TT * HH;

    if (layer == 0) {
        // ============ layer 1: h1 recurrence + Wih2 partials ============
        load_w_async(u_W0, Whh1, col0, tid);             // A0: Whh1[0]
        CPA_COMMIT();
        load_wI_async(u_WI, Wih2, col0, tid);            // I0: Wih2[0] slice
        CPA_COMMIT();
        float pre = __ldg(g_pre1 + rm);
        for (int i = tid; i < 2048; i += NTH) hsA[i] = 0.f;   // h1[-1] = 0

#pragma unroll 1
        for (int t = 0; t < TT; t++) {
            const int tn = (t < TT - 1) ? t + 1 : t;

            // wait: peers' h1[t-1]; backpressure on P ring (depth 4)
            waitflag2(f1, 4u * (unsigned)t,
                      f2, (t >= 4) ? 4u * (unsigned)(t - 3) : 0u);
            if (t > 0)
                stage(hsA, g_h1all + ((long)(t - 1) * NGRP) * 2048 + gtile, tid);
            CPA_WAIT(1);                                  // Whh1[t] landed (I_t may pend)
            __syncthreads();                              // hsA + weights visible
            // prefetch Whh1[t+1] now (after critical stage loads retired)
            load_w_async(((t + 1) & 1) ? u_W1 : u_W0,
                         Whh1 + (long)tn * HH * HH, col0, tid);
            CPA_COMMIT();                                 // A_{t+1}

            const float* sW = (t & 1) ? W1 : W0;
            ull a01 = 0ull, a23 = 0ull, a45 = 0ull, a67 = 0ull;
            dot32s(hsA, sW, s, c, a01, a23, a45, a67);
            float r0 = reduce1(red, a01, a23, a45, a67, s, c);
            float h1v = tanhf(pre + r0);
            pre = __ldg(g_pre1 + (long)tn * BB * HH + rm);
            __stcg(g_h1all + ((long)t * NGRP) * 2048 + gtile + tidx, h1v);
            hsP[c * 8 + s] = h1v;                         // local columns tile
            signal(f1);                                   // h1[t] + hsP published

            // ---- Wih2 partial: P = h1[t][:, own64] @ Wih2[t][own64, :] ----
            CPA_WAIT(1);                                  // I_t (Wih2[t] slice) landed
            ull p01 = 0ull, p23 = 0ull;
#pragma unroll
            for (int k = 0; k < 64; k++) {
                ulonglong2 hv = *(const ulonglong2*)(hsP + k * 8 + ph * 4);
                float wk = WI[k * 256 + pj];
                ull wp = pack2(wk, wk);
                p01 = fma2(hv.x, wp, p01);
                p23 = fma2(hv.y, wp, p23);
            }
            float q0, q1, q2, q3;
            unpack2(q0, q1, p01);
            unpack2(q2, q3, p23);
            float* Pd = &g_P[t & 3][grp][sub][0];
            __stcg(Pd + (ph * 4 + 0) * 256 + pj, q0);
            __stcg(Pd + (ph * 4 + 1) * 256 + pj, q1);
            __stcg(Pd + (ph * 4 + 2) * 256 + pj, q2);
            __stcg(Pd + (ph * 4 + 3) * 256 + pj, q3);
            signal(f1p);                                  // sync inside: WI reads done
            load_wI_async(u_WI, Wih2 + (long)tn * DD * HH, col0, tid);
            CPA_COMMIT();                                 // I_{t+1}
        }
    } else {
        // ============ layer 2: h2 recurrence (partials merged) ============
        load_w_async(u_W0, Whh2, col0, tid);             // B0: Whh2[0]
        CPA_COMMIT();
        float bias = __ldg(b2 + col0 + c);
        for (int i = tid; i < 2048; i += NTH) hsA[i] = 0.f;   // h2[-1] = 0

#pragma unroll 1
        for (int t = 0; t < TT; t++) {
            const int tn = (t < TT - 1) ? t + 1 : t;

            // wait: all P[t] written; peers' h2[t-1]
            waitflag2(f1p, 4u * (unsigned)(t + 1),
                      f2, (t > 0) ? 4u * (unsigned)t : 0u);
            if (t > 0)
                stage(hsA, g_h2t[(t - 1) & 1] + gtile, tid);
            // partial sums for this thread's output (row s, col col0+c)
            const float* Pg = &g_P[t & 3][grp][0][0];
            float p0 = __ldcg(Pg + 0 * 2048 + s * 256 + col0 + c);
            float p1 = __ldcg(Pg + 1 * 2048 + s * 256 + col0 + c);
            float p2 = __ldcg(Pg + 2 * 2048 + s * 256 + col0 + c);
            float p3 = __ldcg(Pg + 3 * 2048 + s * 256 + col0 + c);
            CPA_WAIT(0);                                  // Whh2[t] landed
            __syncthreads();                              // hsA + weights visible
            load_w_async(((t + 1) & 1) ? u_W1 : u_W0,
                         Whh2 + (long)tn * HH * HH, col0, tid);
            CPA_COMMIT();                                 // B_{t+1}

            const float* sW = (t & 1) ? W1 : W0;
            ull a01 = 0ull, a23 = 0ull, a45 = 0ull, a67 = 0ull;
            dot32s(hsA, sW, s, c, a01, a23, a45, a67);    // h2[t-1] @ Whh2[t]
            float r0 = reduce1(red, a01, a23, a45, a67, s, c);
            float pre2 = bias + ((p0 + p1) + (p2 + p3));
            float h2v = tanhf(pre2 + r0);
            __stcg(g_h2t[t & 1] + gtile + tidx, h2v);
            if (t == TT - 1) g_h2rm[rm] = h2v;            // final state, row-major
            signal(f2);
            bias = __ldg(b2 + (long)tn * HH + col0 + c);
        }
    }
}

// ---------------- tail kernels: backward single step + fc head ----------------
__global__ __launch_bounds__(256) void k_tail_a(
    const float* __restrict__ x, const float* __restrict__ Wih_b,
    const float* __restrict__ b_b)
{
    __shared__ float sA[64 * 72];
    __shared__ float sW[64 * 72];
    int tile = blockIdx.x;
    int row0 = (tile >> 2) * 64, col0 = (tile & 3) * 64;
    gemm64_body(x + (long)(TT - 1) * DD, (long)TT * DD,
                nullptr, 1 << 30, 0,
                Wih_b + (long)(TT - 1) * DD * HH, HH, 0,
                b_b + (long)(TT - 1) * HH,
                g_h1bk, HH, DD, row0, col0, /*act=*/1, sA, sW);
}

__global__ __launch_bounds__(256) void k_tail_b(
    const float* __restrict__ Wih_b, const float* __restrict__ b_b)
{
    __shared__ float sA[64 * 72];
    __shared__ float sW[64 * 72];
    int tile = blockIdx.x;
    int row0 = (tile >> 2) * 64, col0 = (tile & 3) * 64;
    gemm64_body(g_h1bk, HH,
                nullptr, 1 << 30, 0,
                Wih_b + (long)(TT + TT - 1) * DD * HH, HH, 0,
                b_b + (long)(TT + TT - 1) * HH,
                g_h2bk, HH, HH, row0, col0, /*act=*/1, sA, sW);
}

__global__ __launch_bounds__(256) void k_tail_c(
    const float* __restrict__ fc_w, const float* __restrict__ fc_b,
    float* __restrict__ out)
{
    __shared__ float sA[64 * 72];
    __shared__ float sW[64 * 72];
    int tile = blockIdx.x;
    int row0 = (tile >> 2) * 64, col0 = (tile & 3) * 64;
    gemm64_body(g_h2rm, HH,
                g_h2bk, /*ksplit=*/HH, HH,
                fc_w, 2 * HH, /*wtrans=*/1,
                fc_b,
                out, HH, 2 * HH, row0, col0, /*act=*/0, sA, sW);
}

// ---------------- launcher ----------------
// k_seq stays at launch slot 4 (the profiler's capture slot).
extern "C" void kernel_launch(void* const* d_in, const int* in_sizes, int n_in,
                              void* d_out, int out_size) {
    const float* x     = (const float*)d_in[0];
    const float* Wih_f = (const float*)d_in[1];
    const float* Whh_f = (const float*)d_in[2];
    const float* b_f   = (const float*)d_in[3];
    const float* Wih_b = (const float*)d_in[4];
    // d_in[5] = Whh_b: unused (backward output at t=T-1 starts from h0=0)
    const float* b_b   = (const float*)d_in[6];
    const float* fc_w  = (const float*)d_in[7];
    const float* fc_b  = (const float*)d_in[8];
    float* out = (float*)d_out;
    (void)in_sizes; (void)n_in; (void)out_size;

    static_assert(SMEM_SEQ_BYTES == 223232, "smem layout");
    cudaFuncSetAttribute(k_seq, cudaFuncAttributeMaxDynamicSharedMemorySize,
                         SMEM_SEQ_BYTES);

    k_reset<<<2, 256>>>();
    k_pre<<<dim3(8, TT), 256>>>(x, Wih_f, b_f);
    k_tail_a<<<8, 256>>>(x, Wih_b, b_b);
    k_seq<<<NBLK, NTH, SMEM_SEQ_BYTES>>>(Wih_f, Whh_f, b_f);
    k_tail_b<<<8, 256>>>(Wih_b, b_b);
    k_tail_c<<<8, 256>>>(fc_w, fc_b, out);
}

// round 14
// speedup vs baseline: 1.0014x; 1.0014x over previous
#include <cuda_runtime.h>
#include <cuda_bf16.h>
#include <math.h>

// Problem constants
#define BB 128
#define TT 256
#define DD 256
#define HH 256

#define NBLK 128        // 16 groups x (4 layer-1 CTAs + 4 layer-2 CTAs)
#define NGRP 16
#define NTH  512        // k_seq threads per CTA (16 warps)

typedef unsigned long long ull;

// ---------------- packed f32x2 helpers (Blackwell FFMA2 via PTX) ----------------
__device__ __forceinline__ ull pack2(float lo, float hi) {
    ull r; asm("mov.b64 %0, {%1, %2};" : "=l"(r) : "f"(lo), "f"(hi)); return r;
}
__device__ __forceinline__ void unpack2(float& lo, float& hi, ull v) {
    asm("mov.b64 {%0, %1}, %2;" : "=f"(lo), "=f"(hi) : "l"(v));
}
__device__ __forceinline__ ull fma2(ull a, ull b, ull c) {
    ull d; asm("fma.rn.f32x2 %0, %1, %2, %3;" : "=l"(d) : "l"(a), "l"(b), "l"(c));
    return d;
}

// ---------------- device scratch ----------------
// h tiles in GROUP-TILE layout: [t or buf][grp][col*8 + r] (2048 floats/tile)
__device__ float g_pre1[TT * BB * HH];          // pre1[t][b][h] row-major (incl b1)
__device__ float g_h1all[(long)TT * NGRP * 2048];  // h1[t], non-destructive
__device__ float g_h2t[2][NGRP * 2048];         // h2 ring, depth 2
__device__ float g_P[4][NGRP][4][2048];         // Wih2 partials: [ring][grp][src][r*256+j]
__device__ float g_h2rm[BB * HH];               // final forward h2, row-major
__device__ float g_h1bk[BB * HH];
__device__ float g_h2bk[BB * HH];
__device__ unsigned g_f1[NGRP * 32];            // h1 exchange flags (L1<->L1)
__device__ unsigned g_f1p[NGRP * 32];           // P-ready flags (L1 -> L2)
__device__ unsigned g_f2[NGRP * 32];            // h2 exchange flags (L2<->L2, + backpressure)

// ---------------- reset kernel (per-replay determinism) ----------------
__global__ void k_reset() {
    unsigned i = blockIdx.x * blockDim.x + threadIdx.x;
    if (i < NGRP * 32) { g_f1[i] = 0u; g_f1p[i] = 0u; g_f2[i] = 0u; }
}

// ---------------- release/acquire flag ops ----------------
__device__ __forceinline__ void signal(unsigned* p) {
    __syncthreads();   // all threads' stores precede the release
    if (threadIdx.x == 0)
        asm volatile("red.release.gpu.add.u32 [%0], 1;" :: "l"(p) : "memory");
}
// combined wait on two flags with one barrier
__device__ __forceinline__ void waitflag2(unsigned* pa, unsigned ta,
                                          unsigned* pb, unsigned tb) {
    if (threadIdx.x == 0) {
        unsigned v;
        do { asm volatile("ld.acquire.gpu.u32 %0, [%1];" : "=r"(v) : "l"(pa) : "memory");
        } while (v < ta);
        do { asm volatile("ld.acquire.gpu.u32 %0, [%1];" : "=r"(v) : "l"(pb) : "memory");
        } while (v < tb);
    }
    __syncthreads();
}

// ---------------- cp.async helpers ----------------
__device__ __forceinline__ unsigned smem_u32(const void* p) {
    unsigned a;
    asm("{ .reg .u64 t; cvta.to.shared.u64 t, %1; cvt.u32.u64 %0, t; }"
        : "=r"(a) : "l"(p));
    return a;
}
__device__ __forceinline__ void cpa16(unsigned saddr, const float* gaddr) {
    asm volatile("cp.async.cg.shared.global [%0], [%1], 16;"
                 :: "r"(saddr), "l"(gaddr) : "memory");
}
#define CPA_COMMIT()  asm volatile("cp.async.commit_group;" ::: "memory")
#define CPA_WAIT(n)   asm volatile("cp.async.wait_group %0;" :: "n"(n) : "memory")

// 256k x 64col weight tile -> smem sW[k*64 + c]
__device__ __forceinline__ void load_w_async(unsigned u_sW, const float* __restrict__ W,
                                             int col0, int tid) {
#pragma unroll
    for (int i = 0; i < 8; i++) {
        int chunk = tid + i * NTH;
        int k = chunk >> 4;
        int c4 = (chunk & 15) * 4;
        cpa16(u_sW + (unsigned)(k * 64 + c4) * 4, W + (long)k * HH + col0 + c4);
    }
}
// 64k(rows col0..col0+63) x 256col slice of Wih2 -> smem sWI[k*256 + j]
__device__ __forceinline__ void load_wI_async(unsigned u_sW, const float* __restrict__ W,
                                              int col0, int tid) {
#pragma unroll
    for (int i = 0; i < 8; i++) {
        int chunk = tid + i * NTH;          // 0..4095 float4 chunks
        int k = chunk >> 6;                  // 0..63 local k
        int j4 = chunk & 63;
        cpa16(u_sW + (unsigned)chunk * 16, W + (long)(col0 + k) * HH + j4 * 4);
    }
}

// ---------------- generic 64x64 register-blocked fp32 GEMM tile (FFMA2) ----------------
__device__ __forceinline__ void gemm64_body(
    const float* __restrict__ A, long lda,
    const float* __restrict__ A2, int ksplit, long lda2,
    const float* __restrict__ W, long ldw, int wtrans,
    const float* __restrict__ bias,
    float* __restrict__ C, long ldc,
    int K, int row0, int col0, int act,
    float* sA, float* sW)
{
    const int tid = threadIdx.x;
    const int tx = tid & 15;
    const int ty = tid >> 4;
    ull accp[4][2];
#pragma unroll
    for (int i = 0; i < 4; i++) { accp[i][0] = 0ull; accp[i][1] = 0ull; }

#pragma unroll 1
    for (int k0 = 0; k0 < K; k0 += 64) {
        const float* Ak = A; long ldak = lda; int kb = k0;
        if (A2 != nullptr && k0 >= ksplit) { Ak = A2; ldak = lda2; kb = k0 - ksplit; }

        __syncthreads();
#pragma unroll
        for (int p = 0; p < 4; p++) {
            int i = p * 256 + tid;
            int rr = i >> 4;
            int k4 = i & 15;
            float4 v = *(const float4*)(Ak + (long)(row0 + rr) * ldak + kb + k4 * 4);
            *(float4*)(sA + rr * 72 + k4 * 4) = v;
        }
        if (!wtrans) {
#pragma unroll
            for (int p = 0; p < 16; p++) {
                int i = p * 256 + tid;
                int kk = i >> 6, cc = i & 63;
                sW[kk * 72 + cc] = W[(long)(k0 + kk) * ldw + col0 + cc];
            }
        } else {
#pragma unroll
            for (int p = 0; p < 16; p++) {
                int i = p * 256 + tid;
                int kk = i & 63, cc = i >> 6;
                sW[kk * 72 + cc] = W[(long)(col0 + cc) * ldw + k0 + kk];
            }
        }
        __syncthreads();

#pragma unroll
        for (int k = 0; k < 64; k++) {
            ulonglong2 wv = *(const ulonglong2*)(sW + k * 72 + tx * 4);
#pragma unroll
            for (int i = 0; i < 4; i++) {
                float a = sA[(ty * 4 + i) * 72 + k];
                ull ap = pack2(a, a);
                accp[i][0] = fma2(ap, wv.x, accp[i][0]);
                accp[i][1] = fma2(ap, wv.y, accp[i][1]);
            }
        }
    }

#pragma unroll
    for (int i = 0; i < 4; i++) {
        float v0, v1, v2, v3;
        unpack2(v0, v1, accp[i][0]);
        unpack2(v2, v3, accp[i][1]);
        float vv[4] = {v0, v1, v2, v3};
#pragma unroll
        for (int j = 0; j < 4; j++) {
            int rr = row0 + ty * 4 + i;
            int cc = col0 + tx * 4 + j;
            float v = vv[j] + bias[cc];
            if (act) v = tanhf(v);
            C[(long)rr * ldc + cc] = v;
        }
    }
}

// ---------------- K1: precompute pre1[t] = x_t @ Wih_f[0,t] + b_f[0,t] ----------------
__global__ __launch_bounds__(256) void k_pre(
    const float* __restrict__ x, const float* __restrict__ Wih_f,
    const float* __restrict__ b_f)
{
    __shared__ float sA[64 * 72];
    __shared__ float sW[64 * 72];
    int t = blockIdx.y;
    int tile = blockIdx.x;
    int row0 = (tile >> 2) * 64;
    int col0 = (tile & 3) * 64;
    gemm64_body(x + (long)t * DD, (long)TT * DD,
                nullptr, 1 << 30, 0,
                Wih_f + (long)t * DD * HH, HH, 0,
                b_f + (long)t * HH,
                g_pre1 + (long)t * BB * HH, HH,
                DD, row0, col0, /*act=*/0, sA, sW);
}

// ================= K2: rebalanced layer-split wavefront =================
// L1 CTAs (sub 0-3) now ALSO compute the Wih2 split-K partials: their own 64
// h1-columns are exactly a 64-wide k-slice of h1[t] @ Wih2[t], available
// locally (no exchange). L2 CTAs (sub 4-7) just sum 4 partials + do the Whh2
// dot — the system period = L2 chain loses one full wait+stage+dot.
// P ring depth 4 with f2 backpressure. Weight cp.async issued AFTER staging
// loads (keeps critical LDGs out of the L1tex queue shadow).

// stage a 2048-float group tile (layout matches smem exactly)
__device__ __forceinline__ void stage(float* dst, const float* __restrict__ src,
                                      int tid) {
    float4 v = __ldcg((const float4*)(src + tid * 4));
    *(float4*)(dst + tid * 4) = v;
}

// packed dot over this thread's 32-k slice; h tile hsT[k*8+r], weights sW[k*64+c]
__device__ __forceinline__ void dot32s(const float* hsT, const float* sW,
                                       int s, int c,
                                       ull& a01, ull& a23, ull& a45, ull& a67) {
#pragma unroll
    for (int kk = 0; kk < 32; kk++) {
        int k = s * 32 + kk;
        const ulonglong2* p = (const ulonglong2*)(hsT + k * 8);
        ulonglong2 v0 = p[0];
        ulonglong2 v1 = p[1];
        float wk = sW[k * 64 + c];
        ull wp = pack2(wk, wk);
        a01 = fma2(v0.x, wp, a01);
        a23 = fma2(v0.y, wp, a23);
        a45 = fma2(v1.x, wp, a45);
        a67 = fma2(v1.y, wp, a67);
    }
}

// split-K reduce over 8 slices: thread (s,c) finalizes output (row=s, col=c)
__device__ __forceinline__ float reduce1(float* red, ull a01, ull a23, ull a45, ull a67,
                                         int s, int c) {
    float r[8];
    unpack2(r[0], r[1], a01);
    unpack2(r[2], r[3], a23);
    unpack2(r[4], r[5], a45);
    unpack2(r[6], r[7], a67);
#pragma unroll
    for (int q = 0; q < 8; q++) red[(s * 8 + q) * 64 + c] = r[q];
    __syncthreads();
    float v = 0.f;
#pragma unroll
    for (int q = 0; q < 8; q++) v += red[(q * 8 + s) * 64 + c];
    return v;
}

// dyn smem (floats): hsA 2048 | hsP 512 | red 4096 | W0 16384 | W1 16384 | WI 16384
#define SMEM_SEQ_BYTES ((2048 + 512 + 4096 + 16384 * 3) * 4)

__global__ __launch_bounds__(NTH, 1)
void k_seq(const float* __restrict__ Wih_f, const float* __restrict__ Whh_f,
           const float* __restrict__ b_f)
{
    extern __shared__ float dyn[];
    float* hsA = dyn;                   // L1: h1 tile | L2: h2 tile
    float* hsP = dyn + 2048;            // L1: local h1 columns [c*8+r]
    float* red = dyn + 2560;            // split-K scratch
    float* W0  = dyn + 6656;            // double buffer 0 (Whh1 / Whh2)
    float* W1  = W0 + 16384;            // double buffer 1
    float* WI  = W1 + 16384;            // L1: Wih2 k-slice [k*256+j] (single)
    const unsigned u_W0 = smem_u32(W0);
    const unsigned u_W1 = smem_u32(W1);
    const unsigned u_WI = smem_u32(WI);

    const int tid = threadIdx.x;
    const int s = tid >> 6;                              // 0..7 k-slice / out row
    const int c = tid & 63;                              // column
    const int pj = tid & 255;                            // dotP: output col 0..255
    const int ph = tid >> 8;                             // dotP: row half (0/1)
    const int grp = blockIdx.x >> 3;
    const int sub = blockIdx.x & 7;
    const int layer = sub >> 2;
    const int col0 = (sub & 3) * 64;
    const int row_base = grp * 8;
    const int tidx = (col0 + c) * 8 + s;                 // tile slot (row s)
    const int rm = (row_base + s) * HH + col0 + c;       // row-major (pre1)
    const long gtile = (long)grp * 2048;
    unsigned* f1  = &g_f1[grp * 32];
    unsigned* f1p = &g_f1p[grp * 32];
    unsigned* f2  = &g_f2[grp * 32];

    const float* Whh1 = Whh_f;
    const float* Wih2 = Wih_f + (long)TT * DD * HH;
    const float* Whh2 = Whh_f + (long)TT * HH * HH;
    const float* b2   = b_f + (long)TT * HH;

    if (layer == 0) {
        // ============ layer 1: h1 recurrence + Wih2 partials ============
        load_w_async(u_W0, Whh1, col0, tid);             // A0: Whh1[0]
        CPA_COMMIT();
        load_wI_async(u_WI, Wih2, col0, tid);            // I0: Wih2[0] slice
        CPA_COMMIT();
        float pre = __ldg(g_pre1 + rm);
        for (int i = tid; i < 2048; i += NTH) hsA[i] = 0.f;   // h1[-1] = 0

#pragma unroll 1
        for (int t = 0; t < TT; t++) {
            const int tn = (t < TT - 1) ? t + 1 : t;

            // wait: peers' h1[t-1]; backpressure on P ring (depth 4)
            waitflag2(f1, 4u * (unsigned)t,
                      f2, (t >= 4) ? 4u * (unsigned)(t - 3) : 0u);
            if (t > 0)
                stage(hsA, g_h1all + ((long)(t - 1) * NGRP) * 2048 + gtile, tid);
            CPA_WAIT(1);                                  // Whh1[t] landed (I_t may pend)
            __syncthreads();                              // hsA + weights visible
            // prefetch Whh1[t+1] now (after critical stage loads retired)
            load_w_async(((t + 1) & 1) ? u_W1 : u_W0,
                         Whh1 + (long)tn * HH * HH, col0, tid);
            CPA_COMMIT();                                 // A_{t+1}

            const float* sW = (t & 1) ? W1 : W0;
            ull a01 = 0ull, a23 = 0ull, a45 = 0ull, a67 = 0ull;
            dot32s(hsA, sW, s, c, a01, a23, a45, a67);
            float r0 = reduce1(red, a01, a23, a45, a67, s, c);
            float h1v = tanhf(pre + r0);
            pre = __ldg(g_pre1 + (long)tn * BB * HH + rm);
            __stcg(g_h1all + ((long)t * NGRP) * 2048 + gtile + tidx, h1v);
            hsP[c * 8 + s] = h1v;                         // local columns tile
            signal(f1);                                   // h1[t] + hsP published

            // ---- Wih2 partial: P = h1[t][:, own64] @ Wih2[t][own64, :] ----
            CPA_WAIT(1);                                  // I_t (Wih2[t] slice) landed
            ull p01 = 0ull, p23 = 0ull;
#pragma unroll
            for (int k = 0; k < 64; k++) {
                ulonglong2 hv = *(const ulonglong2*)(hsP + k * 8 + ph * 4);
                float wk = WI[k * 256 + pj];
                ull wp = pack2(wk, wk);
                p01 = fma2(hv.x, wp, p01);
                p23 = fma2(hv.y, wp, p23);
            }
            float q0, q1, q2, q3;
            unpack2(q0, q1, p01);
            unpack2(q2, q3, p23);
            float* Pd = &g_P[t & 3][grp][sub][0];
            __stcg(Pd + (ph * 4 + 0) * 256 + pj, q0);
            __stcg(Pd + (ph * 4 + 1) * 256 + pj, q1);
            __stcg(Pd + (ph * 4 + 2) * 256 + pj, q2);
            __stcg(Pd + (ph * 4 + 3) * 256 + pj, q3);
            signal(f1p);                                  // sync inside: WI reads done
            load_wI_async(u_WI, Wih2 + (long)tn * DD * HH, col0, tid);
            CPA_COMMIT();                                 // I_{t+1}
        }
    } else {
        // ============ layer 2: h2 recurrence (partials merged) ============
        load_w_async(u_W0, Whh2, col0, tid);             // B0: Whh2[0]
        CPA_COMMIT();
        float bias = __ldg(b2 + col0 + c);
        for (int i = tid; i < 2048; i += NTH) hsA[i] = 0.f;   // h2[-1] = 0

#pragma unroll 1
        for (int t = 0; t < TT; t++) {
            const int tn = (t < TT - 1) ? t + 1 : t;

            // wait: all P[t] written; peers' h2[t-1]
            waitflag2(f1p, 4u * (unsigned)(t + 1),
                      f2, (t > 0) ? 4u * (unsigned)t : 0u);
            if (t > 0)
                stage(hsA, g_h2t[(t - 1) & 1] + gtile, tid);
            // partial sums for this thread's output (row s, col col0+c)
            const float* Pg = &g_P[t & 3][grp][0][0];
            float p0 = __ldcg(Pg + 0 * 2048 + s * 256 + col0 + c);
            float p1 = __ldcg(Pg + 1 * 2048 + s * 256 + col0 + c);
            float p2 = __ldcg(Pg + 2 * 2048 + s * 256 + col0 + c);
            float p3 = __ldcg(Pg + 3 * 2048 + s * 256 + col0 + c);
            CPA_WAIT(0);                                  // Whh2[t] landed
            __syncthreads();                              // hsA + weights visible
            load_w_async(((t + 1) & 1) ? u_W1 : u_W0,
                         Whh2 + (long)tn * HH * HH, col0, tid);
            CPA_COMMIT();                                 // B_{t+1}

            const float* sW = (t & 1) ? W1 : W0;
            ull a01 = 0ull, a23 = 0ull, a45 = 0ull, a67 = 0ull;
            dot32s(hsA, sW, s, c, a01, a23, a45, a67);    // h2[t-1] @ Whh2[t]
            float r0 = reduce1(red, a01, a23, a45, a67, s, c);
            float pre2 = bias + ((p0 + p1) + (p2 + p3));
            float h2v = tanhf(pre2 + r0);
            __stcg(g_h2t[t & 1] + gtile + tidx, h2v);
            if (t == TT - 1) g_h2rm[rm] = h2v;            // final state, row-major
            signal(f2);
            bias = __ldg(b2 + (long)tn * HH + col0 + c);
        }
    }
}

// ---------------- tail kernels: backward single step + fc head ----------------
__global__ __launch_bounds__(256) void k_tail_a(
    const float* __restrict__ x, const float* __restrict__ Wih_b,
    const float* __restrict__ b_b)
{
    __shared__ float sA[64 * 72];
    __shared__ float sW[64 * 72];
    int tile = blockIdx.x;
    int row0 = (tile >> 2) * 64, col0 = (tile & 3) * 64;
    gemm64_body(x + (long)(TT - 1) * DD, (long)TT * DD,
                nullptr, 1 << 30, 0,
                Wih_b + (long)(TT - 1) * DD * HH, HH, 0,
                b_b + (long)(TT - 1) * HH,
                g_h1bk, HH, DD, row0, col0, /*act=*/1, sA, sW);
}

__global__ __launch_bounds__(256) void k_tail_b(
    const float* __restrict__ Wih_b, const float* __restrict__ b_b)
{
    __shared__ float sA[64 * 72];
    __shared__ float sW[64 * 72];
    int tile = blockIdx.x;
    int row0 = (tile >> 2) * 64, col0 = (tile & 3) * 64;
    gemm64_body(g_h1bk, HH,
                nullptr, 1 << 30, 0,
                Wih_b + (long)(TT + TT - 1) * DD * HH, HH, 0,
                b_b + (long)(TT + TT - 1) * HH,
                g_h2bk, HH, HH, row0, col0, /*act=*/1, sA, sW);
}

__global__ __launch_bounds__(256) void k_tail_c(
    const float* __restrict__ fc_w, const float* __restrict__ fc_b,
    float* __restrict__ out)
{
    __shared__ float sA[64 * 72];
    __shared__ float sW[64 * 72];
    int tile = blockIdx.x;
    int row0 = (tile >> 2) * 64, col0 = (tile & 3) * 64;
    gemm64_body(g_h2rm, HH,
                g_h2bk, /*ksplit=*/HH, HH,
                fc_w, 2 * HH, /*wtrans=*/1,
                fc_b,
                out, HH, 2 * HH, row0, col0, /*act=*/0, sA, sW);
}

// ---------------- launcher ----------------
// k_seq stays at launch slot 4 (the profiler's capture slot).
extern "C" void kernel_launch(void* const* d_in, const int* in_sizes, int n_in,
                              void* d_out, int out_size) {
    const float* x     = (const float*)d_in[0];
    const float* Wih_f = (const float*)d_in[1];
    const float* Whh_f = (const float*)d_in[2];
    const float* b_f   = (const float*)d_in[3];
    const float* Wih_b = (const float*)d_in[4];
    // d_in[5] = Whh_b: unused (backward output at t=T-1 starts from h0=0)
    const float* b_b   = (const float*)d_in[6];
    const float* fc_w  = (const float*)d_in[7];
    const float* fc_b  = (const float*)d_in[8];
    float* out = (float*)d_out;
    (void)in_sizes; (void)n_in; (void)out_size;

    static_assert(SMEM_SEQ_BYTES == 223232, "smem layout");
    cudaFuncSetAttribute(k_seq, cudaFuncAttributeMaxDynamicSharedMemorySize,
                         SMEM_SEQ_BYTES);

    k_reset<<<2, 256>>>();
    k_pre<<<dim3(8, TT), 256>>>(x, Wih_f, b_f);
    k_tail_a<<<8, 256>>>(x, Wih_b, b_b);
    k_seq<<<NBLK, NTH, SMEM_SEQ_BYTES>>>(Wih_f, Whh_f, b_f);
    k_tail_b<<<8, 256>>>(Wih_b, b_b);
    k_tail_c<<<8, 256>>>(fc_w, fc_b, out);
}

// round 15
// speedup vs baseline: 1.0918x; 1.0902x over previous
#include <cuda_runtime.h>
#include <cuda_bf16.h>
#include <math.h>

// Problem constants
#define BB 128
#define TT 256
#define DD 256
#define HH 256

#define NBLK 128        // 16 groups x (4 layer-1 CTAs + 4 layer-2 CTAs)
#define NGRP 16
#define NTH  512

typedef unsigned long long ull;

// ---------------- packed f32x2 helpers ----------------
__device__ __forceinline__ ull pack2(float lo, float hi) {
    ull r; asm("mov.b64 %0, {%1, %2};" : "=l"(r) : "f"(lo), "f"(hi)); return r;
}
__device__ __forceinline__ void unpack2(float& lo, float& hi, ull v) {
    asm("mov.b64 {%0, %1}, %2;" : "=f"(lo), "=f"(hi) : "l"(v));
}
__device__ __forceinline__ ull fma2(ull a, ull b, ull c) {
    ull d; asm("fma.rn.f32x2 %0, %1, %2, %3;" : "=l"(d) : "l"(a), "l"(b), "l"(c));
    return d;
}

// ---------------- device scratch ----------------
__device__ float g_pre1[TT * BB * HH];        // pre1[t][b][h] row-major (incl b1)
__device__ float g_P1[2][NGRP][4][2048];      // Whh1 partials  [ring2][grp][src][row*256+col]
__device__ float g_P [4][NGRP][4][2048];      // Wih2 partials  [ring4][grp][src][row*256+col]
__device__ float g_P2[2][NGRP][4][2048];      // Whh2 partials  [ring2][grp][src][row*256+col]
__device__ float g_h2rm[BB * HH];             // final forward h2, row-major
__device__ float g_h1bk[BB * HH];
__device__ float g_h2bk[BB * HH];
__device__ unsigned g_f1[NGRP * 32];          // partial1 ready
__device__ unsigned g_f1p[NGRP * 32];         // P ready
__device__ unsigned g_f2[NGRP * 32];          // partial2 ready / L2 step done

// ---------------- reset kernel ----------------
__global__ void k_reset() {
    unsigned i = blockIdx.x * blockDim.x + threadIdx.x;
    if (i < NGRP * 32) { g_f1[i] = 0u; g_f1p[i] = 0u; g_f2[i] = 0u; }
}

// ---------------- release/acquire flag ops ----------------
__device__ __forceinline__ void signal(unsigned* p) {
    __syncthreads();
    if (threadIdx.x == 0)
        asm volatile("red.release.gpu.add.u32 [%0], 1;" :: "l"(p) : "memory");
}
__device__ __forceinline__ void waitflag2(unsigned* pa, unsigned ta,
                                          unsigned* pb, unsigned tb) {
    if (threadIdx.x == 0) {
        unsigned v;
        do { asm volatile("ld.acquire.gpu.u32 %0, [%1];" : "=r"(v) : "l"(pa) : "memory");
        } while (v < ta);
        do { asm volatile("ld.acquire.gpu.u32 %0, [%1];" : "=r"(v) : "l"(pb) : "memory");
        } while (v < tb);
    }
    __syncthreads();
}

// ---------------- cp.async helpers ----------------
__device__ __forceinline__ unsigned smem_u32(const void* p) {
    unsigned a;
    asm("{ .reg .u64 t; cvta.to.shared.u64 t, %1; cvt.u32.u64 %0, t; }"
        : "=r"(a) : "l"(p));
    return a;
}
__device__ __forceinline__ void cpa16(unsigned saddr, const float* gaddr) {
    asm volatile("cp.async.cg.shared.global [%0], [%1], 16;"
                 :: "r"(saddr), "l"(gaddr) : "memory");
}
#define CPA_COMMIT()  asm volatile("cp.async.commit_group;" ::: "memory")
#define CPA_WAIT(n)   asm volatile("cp.async.wait_group %0;" :: "n"(n) : "memory")

// 64k x 256col weight slice -> smem sW[k*256 + j]; Wbase points at slice origin
__device__ __forceinline__ void load_slice(unsigned u_sW, const float* __restrict__ Wbase,
                                           int tid) {
#pragma unroll
    for (int i = 0; i < 8; i++) {
        int chunk = tid + i * NTH;          // 0..4095 float4 chunks
        int k = chunk >> 6;
        int j4 = (chunk & 63) * 4;
        cpa16(u_sW + (unsigned)chunk * 16, Wbase + (long)k * HH + j4);
    }
}

// ---------------- generic 64x64 register-blocked fp32 GEMM tile (FFMA2) ----------------
__device__ __forceinline__ void gemm64_body(
    const float* __restrict__ A, long lda,
    const float* __restrict__ A2, int ksplit, long lda2,
    const float* __restrict__ W, long ldw, int wtrans,
    const float* __restrict__ bias,
    float* __restrict__ C, long ldc,
    int K, int row0, int col0, int act,
    float* sA, float* sW)
{
    const int tid = threadIdx.x;
    const int tx = tid & 15;
    const int ty = tid >> 4;
    ull accp[4][2];
#pragma unroll
    for (int i = 0; i < 4; i++) { accp[i][0] = 0ull; accp[i][1] = 0ull; }

#pragma unroll 1
    for (int k0 = 0; k0 < K; k0 += 64) {
        const float* Ak = A; long ldak = lda; int kb = k0;
        if (A2 != nullptr && k0 >= ksplit) { Ak = A2; ldak = lda2; kb = k0 - ksplit; }

        __syncthreads();
#pragma unroll
        for (int p = 0; p < 4; p++) {
            int i = p * 256 + tid;
            int rr = i >> 4;
            int k4 = i & 15;
            float4 v = *(const float4*)(Ak + (long)(row0 + rr) * ldak + kb + k4 * 4);
            *(float4*)(sA + rr * 72 + k4 * 4) = v;
        }
        if (!wtrans) {
#pragma unroll
            for (int p = 0; p < 16; p++) {
                int i = p * 256 + tid;
                int kk = i >> 6, cc = i & 63;
                sW[kk * 72 + cc] = W[(long)(k0 + kk) * ldw + col0 + cc];
            }
        } else {
#pragma unroll
            for (int p = 0; p < 16; p++) {
                int i = p * 256 + tid;
                int kk = i & 63, cc = i >> 6;
                sW[kk * 72 + cc] = W[(long)(col0 + cc) * ldw + k0 + kk];
            }
        }
        __syncthreads();

#pragma unroll
        for (int k = 0; k < 64; k++) {
            ulonglong2 wv = *(const ulonglong2*)(sW + k * 72 + tx * 4);
#pragma unroll
            for (int i = 0; i < 4; i++) {
                float a = sA[(ty * 4 + i) * 72 + k];
                ull ap = pack2(a, a);
                accp[i][0] = fma2(ap, wv.x, accp[i][0]);
                accp[i][1] = fma2(ap, wv.y, accp[i][1]);
            }
        }
    }

#pragma unroll
    for (int i = 0; i < 4; i++) {
        float v0, v1, v2, v3;
        unpack2(v0, v1, accp[i][0]);
        unpack2(v2, v3, accp[i][1]);
        float vv[4] = {v0, v1, v2, v3};
#pragma unroll
        for (int j = 0; j < 4; j++) {
            int rr = row0 + ty * 4 + i;
            int cc = col0 + tx * 4 + j;
            float v = vv[j] + bias[cc];
            if (act) v = tanhf(v);
            C[(long)rr * ldc + cc] = v;
        }
    }
}

// ---------------- K1: precompute pre1[t] ----------------
__global__ __launch_bounds__(256) void k_pre(
    const float* __restrict__ x, const float* __restrict__ Wih_f,
    const float* __restrict__ b_f)
{
    __shared__ float sA[64 * 72];
    __shared__ float sW[64 * 72];
    int t = blockIdx.y;
    int tile = blockIdx.x;
    int row0 = (tile >> 2) * 64;
    int col0 = (tile & 3) * 64;
    gemm64_body(x + (long)t * DD, (long)TT * DD,
                nullptr, 1 << 30, 0,
                Wih_f + (long)t * DD * HH, HH, 0,
                b_f + (long)t * HH,
                g_pre1 + (long)t * BB * HH, HH,
                DD, row0, col0, /*act=*/0, sA, sW);
}

// ================= K2: k-split-ownership wavefront =================
// Group g: 8 batch rows. CTA sub 0-3 = L1 (owns h1 cols 64r..), 4-7 = L2 (h2).
// Each CTA's GEMM k-slice input = its OWN h columns (local smem) -> the dot
// needs NO wait/stage. Exchange = 8KB partial store + 2KB own-range gather.
// L1 fuses Whh1[t]-partial and Wih2[t-1]-P-partial over the same h1[t-1] input.

// smem (floats): hsO 512 | sW0 16384 | sW1 16384 | sWI 16384
#define SMEM_SEQ_BYTES ((512 + 16384 * 3) * 4)

__global__ __launch_bounds__(NTH, 1)
void k_seq(const float* __restrict__ Wih_f, const float* __restrict__ Whh_f,
           const float* __restrict__ b_f)
{
    extern __shared__ float dyn[];
    float* hsO = dyn;                   // own h cols [kl*8 + row], 64x8
    float* W0  = dyn + 512;             // Whh slice double buffer 0
    float* W1  = W0 + 16384;            // Whh slice double buffer 1
    float* WI  = W1 + 16384;            // L1 only: Wih2 slice (single)
    const unsigned u_W0 = smem_u32(W0);
    const unsigned u_W1 = smem_u32(W1);
    const unsigned u_WI = smem_u32(WI);

    const int tid = threadIdx.x;
    const int ph = tid >> 8;                             // dot: rows 4ph..4ph+3
    const int pj = tid & 255;                            // dot: output col
    const int rowS = tid >> 6;                           // sum: row 0..7
    const int cS = tid & 63;                             // sum: own col 0..63
    const int grp = blockIdx.x >> 3;
    const int sub = blockIdx.x & 7;
    const int layer = sub >> 2;
    const int r = sub & 3;                               // own cols 64r..64r+63
    const int row_base = grp * 8;
    const int rmS = (row_base + rowS) * HH + 64 * r + cS;  // row-major slot
    unsigned* f1  = &g_f1[grp * 32];
    unsigned* f1p = &g_f1p[grp * 32];
    unsigned* f2  = &g_f2[grp * 32];

    const float* Whh1 = Whh_f;
    const float* Wih2 = Wih_f + (long)TT * DD * HH;
    const float* Whh2 = Whh_f + (long)TT * HH * HH;
    const float* b2   = b_f + (long)TT * HH;
    const long sliceoff = (long)(64 * r) * HH;           // slice row origin

    if (layer == 0) {
        // ============ layer 1: own-cols recurrence + fused Wih2 partial ============
        load_slice(u_W0, Whh1 + sliceoff, tid);          // Whh1[0] slice
        CPA_COMMIT();
        load_slice(u_WI, Wih2 + sliceoff, tid);          // Wih2[0] slice (for t=1's P[0])
        CPA_COMMIT();
        for (int i = tid; i < 512; i += NTH) hsO[i] = 0.f;   // h1[-1] own cols = 0
        float pre = __ldg(g_pre1 + rmS);

#pragma unroll 1
        for (int t = 0; t < TT; t++) {
            const int tn = (t < TT - 1) ? t + 1 : t;

            CPA_WAIT(0);
            __syncthreads();                              // weights + hsO visible
            load_slice(((t + 1) & 1) ? u_W1 : u_W0,       // Whh1[t+1] (other buf)
                       Whh1 + (long)tn * HH * HH + sliceoff, tid);
            CPA_COMMIT();

            // fused dot: partial1 = hsO @ Whh1[t]slice ; Pacc = hsO @ Wih2[t-1]slice
            const float* sWA = (t & 1) ? W1 : W0;
            ull aA0 = 0ull, aA1 = 0ull, aI0 = 0ull, aI1 = 0ull;
#pragma unroll
            for (int kl = 0; kl < 64; kl++) {
                ulonglong2 hv = *(const ulonglong2*)(hsO + kl * 8 + 4 * ph);
                float wA = sWA[kl * 256 + pj];
                float wI = WI[kl * 256 + pj];
                ull wAp = pack2(wA, wA);
                ull wIp = pack2(wI, wI);
                aA0 = fma2(hv.x, wAp, aA0);
                aA1 = fma2(hv.y, wAp, aA1);
                aI0 = fma2(hv.x, wIp, aI0);
                aI1 = fma2(hv.y, wIp, aI1);
            }
            {   // store partial1[t]
                float q0, q1, q2, q3;
                unpack2(q0, q1, aA0);
                unpack2(q2, q3, aA1);
                float* d = &g_P1[t & 1][grp][r][0];
                __stcg(d + (ph * 4 + 0) * 256 + pj, q0);
                __stcg(d + (ph * 4 + 1) * 256 + pj, q1);
                __stcg(d + (ph * 4 + 2) * 256 + pj, q2);
                __stcg(d + (ph * 4 + 3) * 256 + pj, q3);
            }
            signal(f1);                                   // sync inside: dot reads done
            if (t > 0) {                                  // store P[t-1]
                float q0, q1, q2, q3;
                unpack2(q0, q1, aI0);
                unpack2(q2, q3, aI1);
                float* d = &g_P[(t - 1) & 3][grp][r][0];
                __stcg(d + (ph * 4 + 0) * 256 + pj, q0);
                __stcg(d + (ph * 4 + 1) * 256 + pj, q1);
                __stcg(d + (ph * 4 + 2) * 256 + pj, q2);
                __stcg(d + (ph * 4 + 3) * 256 + pj, q3);
                signal(f1p);
            }
            load_slice(u_WI, Wih2 + (long)t * DD * HH + sliceoff, tid);  // Wih2[t]
            CPA_COMMIT();

            // wait peers' partial1[t]; f2 backpressure licenses P-ring reuse
            waitflag2(f1, 4u * (unsigned)(t + 1),
                      f2, (t >= 2) ? 4u * (unsigned)(t - 2) : 0u);
            float sum = pre;
#pragma unroll
            for (int src = 0; src < 4; src++)
                sum += __ldcg(&g_P1[t & 1][grp][src][rowS * 256 + 64 * r + cS]);
            float h1v = tanhf(sum);
            hsO[cS * 8 + rowS] = h1v;
            pre = __ldg(g_pre1 + (long)tn * BB * HH + rmS);
            __syncthreads();                              // hsO ready for next dot
        }
        // epilogue: P[TT-1] = h1[TT-1] @ Wih2[TT-1]
        CPA_WAIT(0);
        __syncthreads();
        ull aI0 = 0ull, aI1 = 0ull;
#pragma unroll
        for (int kl = 0; kl < 64; kl++) {
            ulonglong2 hv = *(const ulonglong2*)(hsO + kl * 8 + 4 * ph);
            float wI = WI[kl * 256 + pj];
            ull wIp = pack2(wI, wI);
            aI0 = fma2(hv.x, wIp, aI0);
            aI1 = fma2(hv.y, wIp, aI1);
        }
        float q0, q1, q2, q3;
        unpack2(q0, q1, aI0);
        unpack2(q2, q3, aI1);
        float* d = &g_P[(TT - 1) & 3][grp][r][0];
        __stcg(d + (ph * 4 + 0) * 256 + pj, q0);
        __stcg(d + (ph * 4 + 1) * 256 + pj, q1);
        __stcg(d + (ph * 4 + 2) * 256 + pj, q2);
        __stcg(d + (ph * 4 + 3) * 256 + pj, q3);
        signal(f1p);
    } else {
        // ============ layer 2: own-cols h2 recurrence ============
        load_slice(u_W0, Whh2 + sliceoff, tid);          // Whh2[0] slice
        CPA_COMMIT();
        for (int i = tid; i < 512; i += NTH) hsO[i] = 0.f;   // h2[-1] own cols = 0
        float biasv = __ldg(b2 + 64 * r + cS);

#pragma unroll 1
        for (int u = 0; u < TT; u++) {
            const int un = (u < TT - 1) ? u + 1 : u;

            CPA_WAIT(0);
            __syncthreads();
            load_slice(((u + 1) & 1) ? u_W1 : u_W0,
                       Whh2 + (long)un * HH * HH + sliceoff, tid);
            CPA_COMMIT();

            const float* sWB = (u & 1) ? W1 : W0;
            ull a0 = 0ull, a1 = 0ull;
#pragma unroll
            for (int kl = 0; kl < 64; kl++) {
                ulonglong2 hv = *(const ulonglong2*)(hsO + kl * 8 + 4 * ph);
                float w = sWB[kl * 256 + pj];
                ull wp = pack2(w, w);
                a0 = fma2(hv.x, wp, a0);
                a1 = fma2(hv.y, wp, a1);
            }
            {   // store partial2[u]
                float q0, q1, q2, q3;
                unpack2(q0, q1, a0);
                unpack2(q2, q3, a1);
                float* d = &g_P2[u & 1][grp][r][0];
                __stcg(d + (ph * 4 + 0) * 256 + pj, q0);
                __stcg(d + (ph * 4 + 1) * 256 + pj, q1);
                __stcg(d + (ph * 4 + 2) * 256 + pj, q2);
                __stcg(d + (ph * 4 + 3) * 256 + pj, q3);
            }
            signal(f2);

            // wait P[u] (L1, usually ahead) + peers' partial2[u]
            waitflag2(f1p, 4u * (unsigned)(u + 1),
                      f2, 4u * (unsigned)(u + 1));
            float acc = biasv;
#pragma unroll
            for (int src = 0; src < 4; src++)
                acc += __ldcg(&g_P2[u & 1][grp][src][rowS * 256 + 64 * r + cS]);
#pragma unroll
            for (int src = 0; src < 4; src++)
                acc += __ldcg(&g_P[u & 3][grp][src][rowS * 256 + 64 * r + cS]);
            float h2v = tanhf(acc);
            hsO[cS * 8 + rowS] = h2v;
            if (u == TT - 1) g_h2rm[rmS] = h2v;           // final state, row-major
            biasv = __ldg(b2 + (long)un * HH + 64 * r + cS);
            __syncthreads();
        }
    }
}

// ---------------- tail kernels: backward single step + fc head ----------------
__global__ __launch_bounds__(256) void k_tail_a(
    const float* __restrict__ x, const float* __restrict__ Wih_b,
    const float* __restrict__ b_b)
{
    __shared__ float sA[64 * 72];
    __shared__ float sW[64 * 72];
    int tile = blockIdx.x;
    int row0 = (tile >> 2) * 64, col0 = (tile & 3) * 64;
    gemm64_body(x + (long)(TT - 1) * DD, (long)TT * DD,
                nullptr, 1 << 30, 0,
                Wih_b + (long)(TT - 1) * DD * HH, HH, 0,
                b_b + (long)(TT - 1) * HH,
                g_h1bk, HH, DD, row0, col0, /*act=*/1, sA, sW);
}

__global__ __launch_bounds__(256) void k_tail_b(
    const float* __restrict__ Wih_b, const float* __restrict__ b_b)
{
    __shared__ float sA[64 * 72];
    __shared__ float sW[64 * 72];
    int tile = blockIdx.x;
    int row0 = (tile >> 2) * 64, col0 = (tile & 3) * 64;
    gemm64_body(g_h1bk, HH,
                nullptr, 1 << 30, 0,
                Wih_b + (long)(TT + TT - 1) * DD * HH, HH, 0,
                b_b + (long)(TT + TT - 1) * HH,
                g_h2bk, HH, HH, row0, col0, /*act=*/1, sA, sW);
}

__global__ __launch_bounds__(256) void k_tail_c(
    const float* __restrict__ fc_w, const float* __restrict__ fc_b,
    float* __restrict__ out)
{
    __shared__ float sA[64 * 72];
    __shared__ float sW[64 * 72];
    int tile = blockIdx.x;
    int row0 = (tile >> 2) * 64, col0 = (tile & 3) * 64;
    gemm64_body(g_h2rm, HH,
                g_h2bk, /*ksplit=*/HH, HH,
                fc_w, 2 * HH, /*wtrans=*/1,
                fc_b,
                out, HH, 2 * HH, row0, col0, /*act=*/0, sA, sW);
}

// ---------------- launcher (k_seq at profiler capture slot 4) ----------------
extern "C" void kernel_launch(void* const* d_in, const int* in_sizes, int n_in,
                              void* d_out, int out_size) {
    const float* x     = (const float*)d_in[0];
    const float* Wih_f = (const float*)d_in[1];
    const float* Whh_f = (const float*)d_in[2];
    const float* b_f   = (const float*)d_in[3];
    const float* Wih_b = (const float*)d_in[4];
    // d_in[5] = Whh_b: unused (backward output at t=T-1 starts from h0=0)
    const float* b_b   = (const float*)d_in[6];
    const float* fc_w  = (const float*)d_in[7];
    const float* fc_b  = (const float*)d_in[8];
    float* out = (float*)d_out;
    (void)in_sizes; (void)n_in; (void)out_size;

    static_assert(SMEM_SEQ_BYTES == 198656, "smem layout");
    cudaFuncSetAttribute(k_seq, cudaFuncAttributeMaxDynamicSharedMemorySize,
                         SMEM_SEQ_BYTES);

    k_reset<<<2, 256>>>();
    k_pre<<<dim3(8, TT), 256>>>(x, Wih_f, b_f);
    k_tail_a<<<8, 256>>>(x, Wih_b, b_b);
    k_seq<<<NBLK, NTH, SMEM_SEQ_BYTES>>>(Wih_f, Whh_f, b_f);
    k_tail_b<<<8, 256>>>(Wih_b, b_b);
    k_tail_c<<<8, 256>>>(fc_w, fc_b, out);
}